// round 1
// baseline (speedup 1.0000x reference)
#include <cuda_runtime.h>
#include <cstdint>

#define NN 100000
#define NE 640000
#define HID 128

// ---------------- device scratch (static: no allocs allowed) ----------------
__device__ int   g_is64;
__device__ int   g_src[NE];
__device__ int   g_dst[NE];
__device__ int   g_deg[NN];
__device__ int   g_rowptr[NN + 1];
__device__ int   g_cursor[NN];
__device__ int   g_csr[NE];
__device__ float g_z[(size_t)NN * HID];   // x @ W_rel^T
__device__ float g_r[(size_t)NN * HID];   // x @ W_root^T
__device__ float g_hA[(size_t)NN * HID];  // layer0 output
__device__ float g_hB[(size_t)NN * HID];  // layer1 output

// ---------------- helpers ----------------
__device__ __forceinline__ float tf32f(float x) {
    unsigned u;
    asm("cvt.rna.tf32.f32 %0, %1;" : "=r"(u) : "f"(x));
    return __uint_as_float(u);
}

__device__ __forceinline__ void mma_tf32(float c[4], const unsigned a[4], const unsigned b[2]) {
    asm volatile(
        "mma.sync.aligned.m16n8k8.row.col.f32.tf32.tf32.f32 "
        "{%0,%1,%2,%3}, {%4,%5,%6,%7}, {%8,%9}, {%0,%1,%2,%3};\n"
        : "+f"(c[0]), "+f"(c[1]), "+f"(c[2]), "+f"(c[3])
        : "r"(a[0]), "r"(a[1]), "r"(a[2]), "r"(a[3]), "r"(b[0]), "r"(b[1]));
}

// ---------------- edge dtype detect + normalize ----------------
// If edge_index is int64 (little-endian), every odd int32 word of the first
// 128 values is the high word == 0 (node ids < 2^31). For int32 data those
// words are random node ids (P(zero) ~ 1e-5 each).
__global__ void k_detect(const int* __restrict__ e) {
    int zeros = 0;
    for (int i = 1; i < 256; i += 2) zeros += (e[i] == 0);
    g_is64 = (zeros > 100) ? 1 : 0;
}

__global__ void k_convert(const int* __restrict__ e) {
    int i = blockIdx.x * 256 + threadIdx.x;
    if (i < NN) g_deg[i] = 0;
    if (i >= NE) return;
    if (g_is64) {
        g_src[i] = e[2 * i];
        g_dst[i] = e[2 * NE + 2 * i];
    } else {
        g_src[i] = e[i];
        g_dst[i] = e[NE + i];
    }
}

__global__ void k_count() {
    int i = blockIdx.x * 256 + threadIdx.x;
    if (i < NE) atomicAdd(&g_deg[g_dst[i]], 1);
}

// single-block exclusive scan of g_deg -> g_rowptr (+ cursor copy)
__global__ void k_scan() {
    __shared__ int part[1024];
    const int tid = threadIdx.x;
    const int CH = (NN + 1023) / 1024;  // 98
    int beg = tid * CH;
    int s = 0;
    for (int j = 0; j < CH; j++) {
        int i = beg + j;
        if (i < NN) s += g_deg[i];
    }
    part[tid] = s;
    __syncthreads();
    for (int off = 1; off < 1024; off <<= 1) {
        int add = (tid >= off) ? part[tid - off] : 0;
        __syncthreads();
        part[tid] += add;
        __syncthreads();
    }
    int run = (tid > 0) ? part[tid - 1] : 0;
    for (int j = 0; j < CH; j++) {
        int i = beg + j;
        if (i < NN) {
            g_rowptr[i] = run;
            g_cursor[i] = run;
            run += g_deg[i];
        }
    }
    if (tid == 1023) g_rowptr[NN] = part[1023];
}

__global__ void k_fill() {
    int i = blockIdx.x * 256 + threadIdx.x;
    if (i < NE) {
        int d = g_dst[i];
        int p = atomicAdd(&g_cursor[d], 1);
        g_csr[p] = g_src[i];
    }
}

// ---------------- GEMM: Out(100k x 128) = X(100k x 128) @ W^T ----------------
// blockIdx.y == 0 : W = Wrel,  Out = g_z
// blockIdx.y == 1 : W = Wroot, Out = g_r
// tf32 mma with A split hi/lo (x = hi + lo), W single tf32 rounding.
// CTA tile 128x128, 8 warps (2x4), warp tile 64x32, K=128 resident in smem.
#define APAD 132
#define SMEM_BYTES (3 * 128 * APAD * 4)

__global__ __launch_bounds__(256, 1) void k_gemm(const float* __restrict__ X,
                                                 const float* __restrict__ Wrel,
                                                 const float* __restrict__ Wroot) {
    extern __shared__ float sm[];
    float* Ah = sm;                  // 128 x APAD
    float* Al = Ah + 128 * APAD;     // 128 x APAD
    float* Bs = Al + 128 * APAD;     // 128 x APAD  (W rows are N, cols are K)

    const int tid = threadIdx.x;
    const int m0 = blockIdx.x * 128;
    const float* W = (blockIdx.y == 0) ? Wrel : Wroot;
    float* Out = (blockIdx.y == 0) ? g_z : g_r;

    // load + split A tile
    const float4* X4 = (const float4*)X;
    #pragma unroll
    for (int t = tid; t < 128 * 32; t += 256) {
        int row = t >> 5, c4 = t & 31;
        float4 v = make_float4(0.f, 0.f, 0.f, 0.f);
        if (m0 + row < NN) v = X4[(size_t)(m0 + row) * 32 + c4];
        float hx = tf32f(v.x), hy = tf32f(v.y), hz = tf32f(v.z), hw = tf32f(v.w);
        int base = row * APAD + c4 * 4;
        Ah[base + 0] = hx;
        Ah[base + 1] = hy;
        Ah[base + 2] = hz;
        Ah[base + 3] = hw;
        Al[base + 0] = tf32f(v.x - hx);
        Al[base + 1] = tf32f(v.y - hy);
        Al[base + 2] = tf32f(v.z - hz);
        Al[base + 3] = tf32f(v.w - hw);
    }
    // load B tile (W is [128 out][128 in], K-contiguous = col-major B)
    const float4* W4 = (const float4*)W;
    #pragma unroll
    for (int t = tid; t < 128 * 32; t += 256) {
        int row = t >> 5, c4 = t & 31;
        float4 v = W4[t];
        int base = row * APAD + c4 * 4;
        Bs[base + 0] = tf32f(v.x);
        Bs[base + 1] = tf32f(v.y);
        Bs[base + 2] = tf32f(v.z);
        Bs[base + 3] = tf32f(v.w);
    }
    __syncthreads();

    const int wid = tid >> 5, lane = tid & 31;
    const int wm = wid >> 2, wn = wid & 3;
    const int gid = lane >> 2, tig = lane & 3;

    float acc[4][4][4];
    #pragma unroll
    for (int mi = 0; mi < 4; mi++)
        #pragma unroll
        for (int ni = 0; ni < 4; ni++)
            #pragma unroll
            for (int q = 0; q < 4; q++) acc[mi][ni][q] = 0.f;

    #pragma unroll
    for (int p = 0; p < 2; p++) {
        const float* As = p ? Al : Ah;
        #pragma unroll
        for (int kk = 0; kk < 128; kk += 8) {
            unsigned a[4][4], b[4][2];
            #pragma unroll
            for (int mi = 0; mi < 4; mi++) {
                int r0 = (wm * 64 + mi * 16 + gid) * APAD + kk + tig;
                a[mi][0] = __float_as_uint(As[r0]);
                a[mi][1] = __float_as_uint(As[r0 + 8 * APAD]);
                a[mi][2] = __float_as_uint(As[r0 + 4]);
                a[mi][3] = __float_as_uint(As[r0 + 8 * APAD + 4]);
            }
            #pragma unroll
            for (int ni = 0; ni < 4; ni++) {
                int c0 = (wn * 32 + ni * 8 + gid) * APAD + kk + tig;
                b[ni][0] = __float_as_uint(Bs[c0]);
                b[ni][1] = __float_as_uint(Bs[c0 + 4]);
            }
            #pragma unroll
            for (int mi = 0; mi < 4; mi++)
                #pragma unroll
                for (int ni = 0; ni < 4; ni++) mma_tf32(acc[mi][ni], a[mi], b[ni]);
        }
    }

    // epilogue
    #pragma unroll
    for (int mi = 0; mi < 4; mi++) {
        int rbase = m0 + wm * 64 + mi * 16 + gid;
        #pragma unroll
        for (int ni = 0; ni < 4; ni++) {
            int col = wn * 32 + ni * 8 + 2 * tig;
            if (rbase < NN)
                *(float2*)&Out[(size_t)rbase * HID + col] =
                    make_float2(acc[mi][ni][0], acc[mi][ni][1]);
            if (rbase + 8 < NN)
                *(float2*)&Out[(size_t)(rbase + 8) * HID + col] =
                    make_float2(acc[mi][ni][2], acc[mi][ni][3]);
        }
    }
}

// ---------------- gather: out[i] = [relu](r[i] + sum_{e in CSR[i]} z[src_e] + b)
// one warp per node; each lane owns one float4 (4 features)
__global__ __launch_bounds__(256) void k_gather(const float* __restrict__ bias,
                                                float* __restrict__ out, int do_relu) {
    int gw = (blockIdx.x * blockDim.x + threadIdx.x) >> 5;
    int lane = threadIdx.x & 31;
    if (gw >= NN) return;

    int beg = g_rowptr[gw], end = g_rowptr[gw + 1];
    const float4* z4 = (const float4*)g_z;

    float4 a0 = make_float4(0.f, 0.f, 0.f, 0.f);
    float4 a1 = make_float4(0.f, 0.f, 0.f, 0.f);
    int e = beg;
    for (; e + 1 < end; e += 2) {
        int s0 = g_csr[e], s1 = g_csr[e + 1];
        float4 v0 = z4[(size_t)s0 * 32 + lane];
        float4 v1 = z4[(size_t)s1 * 32 + lane];
        a0.x += v0.x; a0.y += v0.y; a0.z += v0.z; a0.w += v0.w;
        a1.x += v1.x; a1.y += v1.y; a1.z += v1.z; a1.w += v1.w;
    }
    if (e < end) {
        int s = g_csr[e];
        float4 v = z4[(size_t)s * 32 + lane];
        a0.x += v.x; a0.y += v.y; a0.z += v.z; a0.w += v.w;
    }

    float4 rr = ((const float4*)g_r)[(size_t)gw * 32 + lane];
    float4 bb = ((const float4*)bias)[lane];
    float4 o;
    o.x = a0.x + a1.x + rr.x + bb.x;
    o.y = a0.y + a1.y + rr.y + bb.y;
    o.z = a0.z + a1.z + rr.z + bb.z;
    o.w = a0.w + a1.w + rr.w + bb.w;
    if (do_relu) {
        o.x = fmaxf(o.x, 0.f);
        o.y = fmaxf(o.y, 0.f);
        o.z = fmaxf(o.z, 0.f);
        o.w = fmaxf(o.w, 0.f);
    }
    ((float4*)out)[(size_t)gw * 32 + lane] = o;
}

// ---------------- launch ----------------
extern "C" void kernel_launch(void* const* d_in, const int* in_sizes, int n_in,
                              void* d_out, int out_size) {
    (void)in_sizes; (void)n_in; (void)out_size;
    const float* x      = (const float*)d_in[0];
    const int*   edges  = (const int*)d_in[1];
    const float* Wrel0  = (const float*)d_in[2];
    const float* b0     = (const float*)d_in[3];
    const float* Wroot0 = (const float*)d_in[4];
    const float* Wrel1  = (const float*)d_in[5];
    const float* b1     = (const float*)d_in[6];
    const float* Wroot1 = (const float*)d_in[7];
    const float* Wrel2  = (const float*)d_in[8];
    const float* b2     = (const float*)d_in[9];
    const float* Wroot2 = (const float*)d_in[10];

    cudaFuncSetAttribute(k_gemm, cudaFuncAttributeMaxDynamicSharedMemorySize, SMEM_BYTES);

    void *pA = nullptr, *pB = nullptr;
    cudaGetSymbolAddress(&pA, g_hA);
    cudaGetSymbolAddress(&pB, g_hB);

    const int eblocks = (NE + 255) / 256;
    k_detect<<<1, 1>>>(edges);
    k_convert<<<eblocks, 256>>>(edges);
    k_count<<<eblocks, 256>>>();
    k_scan<<<1, 1024>>>();
    k_fill<<<eblocks, 256>>>();

    dim3 ggrid((NN + 127) / 128, 2);

    // layer 0
    k_gemm<<<ggrid, 256, SMEM_BYTES>>>(x, Wrel0, Wroot0);
    k_gather<<<(NN + 7) / 8, 256>>>(b0, (float*)pA, 1);
    // layer 1
    k_gemm<<<ggrid, 256, SMEM_BYTES>>>((const float*)pA, Wrel1, Wroot1);
    k_gather<<<(NN + 7) / 8, 256>>>(b1, (float*)pB, 1);
    // layer 2 (no relu)
    k_gemm<<<ggrid, 256, SMEM_BYTES>>>((const float*)pB, Wrel2, Wroot2);
    k_gather<<<(NN + 7) / 8, 256>>>(b2, (float*)d_out, 0);
}

// round 2
// speedup vs baseline: 1.3172x; 1.3172x over previous
#include <cuda_runtime.h>
#include <cstdint>

#define NN 100000
#define NE 640000
#define HID 128
#define SCAN_NB 98   // 98 * 1024 >= NN

// ---------------- device scratch (static: no allocs allowed) ----------------
__device__ int   g_is64;
__device__ int   g_src[NE];
__device__ int   g_dst[NE];
__device__ int   g_deg[NN];
__device__ int   g_part[SCAN_NB];
__device__ int   g_partpre[SCAN_NB];
__device__ int   g_rowptr[NN + 1];
__device__ int   g_cursor[NN];
__device__ int   g_csr[NE];
__device__ float g_z[(size_t)NN * HID];   // x @ W_rel^T
__device__ float g_r[(size_t)NN * HID];   // x @ W_root^T
__device__ float g_hA[(size_t)NN * HID];  // layer0 output
__device__ float g_hB[(size_t)NN * HID];  // layer1 output

// ---------------- helpers ----------------
__device__ __forceinline__ float tf32f(float x) {
    unsigned u;
    asm("cvt.rna.tf32.f32 %0, %1;" : "=r"(u) : "f"(x));
    return __uint_as_float(u);
}

__device__ __forceinline__ void mma_tf32(float c[4], const unsigned a[4], const unsigned b[2]) {
    asm volatile(
        "mma.sync.aligned.m16n8k8.row.col.f32.tf32.tf32.f32 "
        "{%0,%1,%2,%3}, {%4,%5,%6,%7}, {%8,%9}, {%0,%1,%2,%3};\n"
        : "+f"(c[0]), "+f"(c[1]), "+f"(c[2]), "+f"(c[3])
        : "r"(a[0]), "r"(a[1]), "r"(a[2]), "r"(a[3]), "r"(b[0]), "r"(b[1]));
}

// ---------------- edge dtype detect + normalize ----------------
__global__ void k_detect(const int* __restrict__ e) {
    int zeros = 0;
    for (int i = 1; i < 256; i += 2) zeros += (e[i] == 0);
    g_is64 = (zeros > 100) ? 1 : 0;
}

// convert + degree count fused (g_deg pre-zeroed via memsetAsync)
__global__ void k_convert(const int* __restrict__ e) {
    int i = blockIdx.x * 256 + threadIdx.x;
    if (i >= NE) return;
    int s, d;
    if (g_is64) {
        s = e[2 * i];
        d = e[2 * NE + 2 * i];
    } else {
        s = e[i];
        d = e[NE + i];
    }
    g_src[i] = s;
    g_dst[i] = d;
    atomicAdd(&g_deg[d], 1);
}

// ---------------- 3-phase parallel exclusive scan of g_deg ----------------
__global__ __launch_bounds__(1024) void k_scan1() {
    __shared__ int sh[1024];
    int i = blockIdx.x * 1024 + threadIdx.x;
    int v = (i < NN) ? g_deg[i] : 0;
    sh[threadIdx.x] = v;
    __syncthreads();
    #pragma unroll
    for (int off = 512; off > 0; off >>= 1) {
        if (threadIdx.x < off) sh[threadIdx.x] += sh[threadIdx.x + off];
        __syncthreads();
    }
    if (threadIdx.x == 0) g_part[blockIdx.x] = sh[0];
}

__global__ void k_scan2() {
    __shared__ int sh[128];
    int t = threadIdx.x;
    int v = (t < SCAN_NB) ? g_part[t] : 0;
    sh[t] = v;
    __syncthreads();
    #pragma unroll
    for (int off = 1; off < 128; off <<= 1) {
        int add = (t >= off) ? sh[t - off] : 0;
        __syncthreads();
        sh[t] += add;
        __syncthreads();
    }
    if (t < SCAN_NB) g_partpre[t] = sh[t] - v;  // exclusive
    if (t == 127) g_rowptr[NN] = sh[127];
}

__global__ __launch_bounds__(1024) void k_scan3() {
    __shared__ int sh[1024];
    int t = threadIdx.x;
    int i = blockIdx.x * 1024 + t;
    int v = (i < NN) ? g_deg[i] : 0;
    sh[t] = v;
    __syncthreads();
    #pragma unroll
    for (int off = 1; off < 1024; off <<= 1) {
        int add = (t >= off) ? sh[t - off] : 0;
        __syncthreads();
        sh[t] += add;
        __syncthreads();
    }
    if (i < NN) {
        int excl = sh[t] - v + g_partpre[blockIdx.x];
        g_rowptr[i] = excl;
        g_cursor[i] = excl;
    }
}

__global__ void k_fill() {
    int i = blockIdx.x * 256 + threadIdx.x;
    if (i < NE) {
        int d = g_dst[i];
        int p = atomicAdd(&g_cursor[d], 1);
        g_csr[p] = g_src[i];
    }
}

// ---------------- GEMM: Out(100k x 128) = X(100k x 128) @ W^T ----------------
// blockIdx.y == 0 : W = Wrel,  Out = g_z ; blockIdx.y == 1 : W = Wroot, Out = g_r
// tf32 mma with A split hi/lo, W single tf32 rounding.
#define APAD 132
#define SMEM_BYTES (3 * 128 * APAD * 4)

__global__ __launch_bounds__(256, 1) void k_gemm(const float* __restrict__ X,
                                                 const float* __restrict__ Wrel,
                                                 const float* __restrict__ Wroot) {
    extern __shared__ float sm[];
    float* Ah = sm;                  // 128 x APAD
    float* Al = Ah + 128 * APAD;     // 128 x APAD
    float* Bs = Al + 128 * APAD;     // 128 x APAD

    const int tid = threadIdx.x;
    const int m0 = blockIdx.x * 128;
    const float* W = (blockIdx.y == 0) ? Wrel : Wroot;
    float* Out = (blockIdx.y == 0) ? g_z : g_r;

    const float4* X4 = (const float4*)X;
    #pragma unroll
    for (int t = tid; t < 128 * 32; t += 256) {
        int row = t >> 5, c4 = t & 31;
        float4 v = make_float4(0.f, 0.f, 0.f, 0.f);
        if (m0 + row < NN) v = X4[(size_t)(m0 + row) * 32 + c4];
        float hx = tf32f(v.x), hy = tf32f(v.y), hz = tf32f(v.z), hw = tf32f(v.w);
        int base = row * APAD + c4 * 4;
        Ah[base + 0] = hx;
        Ah[base + 1] = hy;
        Ah[base + 2] = hz;
        Ah[base + 3] = hw;
        Al[base + 0] = tf32f(v.x - hx);
        Al[base + 1] = tf32f(v.y - hy);
        Al[base + 2] = tf32f(v.z - hz);
        Al[base + 3] = tf32f(v.w - hw);
    }
    const float4* W4 = (const float4*)W;
    #pragma unroll
    for (int t = tid; t < 128 * 32; t += 256) {
        int row = t >> 5, c4 = t & 31;
        float4 v = W4[t];
        int base = row * APAD + c4 * 4;
        Bs[base + 0] = tf32f(v.x);
        Bs[base + 1] = tf32f(v.y);
        Bs[base + 2] = tf32f(v.z);
        Bs[base + 3] = tf32f(v.w);
    }
    __syncthreads();

    const int wid = tid >> 5, lane = tid & 31;
    const int wm = wid >> 2, wn = wid & 3;
    const int gid = lane >> 2, tig = lane & 3;

    float acc[4][4][4];
    #pragma unroll
    for (int mi = 0; mi < 4; mi++)
        #pragma unroll
        for (int ni = 0; ni < 4; ni++)
            #pragma unroll
            for (int q = 0; q < 4; q++) acc[mi][ni][q] = 0.f;

    #pragma unroll
    for (int p = 0; p < 2; p++) {
        const float* As = p ? Al : Ah;
        #pragma unroll
        for (int kk = 0; kk < 128; kk += 8) {
            unsigned a[4][4], b[4][2];
            #pragma unroll
            for (int mi = 0; mi < 4; mi++) {
                int r0 = (wm * 64 + mi * 16 + gid) * APAD + kk + tig;
                a[mi][0] = __float_as_uint(As[r0]);
                a[mi][1] = __float_as_uint(As[r0 + 8 * APAD]);
                a[mi][2] = __float_as_uint(As[r0 + 4]);
                a[mi][3] = __float_as_uint(As[r0 + 8 * APAD + 4]);
            }
            #pragma unroll
            for (int ni = 0; ni < 4; ni++) {
                int c0 = (wn * 32 + ni * 8 + gid) * APAD + kk + tig;
                b[ni][0] = __float_as_uint(Bs[c0]);
                b[ni][1] = __float_as_uint(Bs[c0 + 4]);
            }
            #pragma unroll
            for (int mi = 0; mi < 4; mi++)
                #pragma unroll
                for (int ni = 0; ni < 4; ni++) mma_tf32(acc[mi][ni], a[mi], b[ni]);
        }
    }

    #pragma unroll
    for (int mi = 0; mi < 4; mi++) {
        int rbase = m0 + wm * 64 + mi * 16 + gid;
        #pragma unroll
        for (int ni = 0; ni < 4; ni++) {
            int col = wn * 32 + ni * 8 + 2 * tig;
            if (rbase < NN)
                *(float2*)&Out[(size_t)rbase * HID + col] =
                    make_float2(acc[mi][ni][0], acc[mi][ni][1]);
            if (rbase + 8 < NN)
                *(float2*)&Out[(size_t)(rbase + 8) * HID + col] =
                    make_float2(acc[mi][ni][2], acc[mi][ni][3]);
        }
    }
}

// ---------------- gather: out[i] = [relu](r[i] + sum_{e in CSR[i]} z[src_e] + b)
__global__ __launch_bounds__(256) void k_gather(const float* __restrict__ bias,
                                                float* __restrict__ out, int do_relu) {
    int gw = (blockIdx.x * blockDim.x + threadIdx.x) >> 5;
    int lane = threadIdx.x & 31;
    if (gw >= NN) return;

    int beg = g_rowptr[gw], end = g_rowptr[gw + 1];
    const float4* z4 = (const float4*)g_z;

    float4 a0 = make_float4(0.f, 0.f, 0.f, 0.f);
    float4 a1 = make_float4(0.f, 0.f, 0.f, 0.f);
    int e = beg;
    for (; e + 1 < end; e += 2) {
        int s0 = g_csr[e], s1 = g_csr[e + 1];
        float4 v0 = z4[(size_t)s0 * 32 + lane];
        float4 v1 = z4[(size_t)s1 * 32 + lane];
        a0.x += v0.x; a0.y += v0.y; a0.z += v0.z; a0.w += v0.w;
        a1.x += v1.x; a1.y += v1.y; a1.z += v1.z; a1.w += v1.w;
    }
    if (e < end) {
        int s = g_csr[e];
        float4 v = z4[(size_t)s * 32 + lane];
        a0.x += v.x; a0.y += v.y; a0.z += v.z; a0.w += v.w;
    }

    float4 rr = ((const float4*)g_r)[(size_t)gw * 32 + lane];
    float4 bb = ((const float4*)bias)[lane];
    float4 o;
    o.x = a0.x + a1.x + rr.x + bb.x;
    o.y = a0.y + a1.y + rr.y + bb.y;
    o.z = a0.z + a1.z + rr.z + bb.z;
    o.w = a0.w + a1.w + rr.w + bb.w;
    if (do_relu) {
        o.x = fmaxf(o.x, 0.f);
        o.y = fmaxf(o.y, 0.f);
        o.z = fmaxf(o.z, 0.f);
        o.w = fmaxf(o.w, 0.f);
    }
    ((float4*)out)[(size_t)gw * 32 + lane] = o;
}

// ---------------- launch ----------------
extern "C" void kernel_launch(void* const* d_in, const int* in_sizes, int n_in,
                              void* d_out, int out_size) {
    (void)in_sizes; (void)n_in; (void)out_size;
    const float* x      = (const float*)d_in[0];
    const int*   edges  = (const int*)d_in[1];
    const float* Wrel0  = (const float*)d_in[2];
    const float* b0     = (const float*)d_in[3];
    const float* Wroot0 = (const float*)d_in[4];
    const float* Wrel1  = (const float*)d_in[5];
    const float* b1     = (const float*)d_in[6];
    const float* Wroot1 = (const float*)d_in[7];
    const float* Wrel2  = (const float*)d_in[8];
    const float* b2     = (const float*)d_in[9];
    const float* Wroot2 = (const float*)d_in[10];

    cudaFuncSetAttribute(k_gemm, cudaFuncAttributeMaxDynamicSharedMemorySize, SMEM_BYTES);

    void *pA = nullptr, *pB = nullptr, *pDeg = nullptr;
    cudaGetSymbolAddress(&pA, g_hA);
    cudaGetSymbolAddress(&pB, g_hB);
    cudaGetSymbolAddress(&pDeg, g_deg);

    const int eblocks = (NE + 255) / 256;
    k_detect<<<1, 1>>>(edges);
    cudaMemsetAsync(pDeg, 0, (size_t)NN * sizeof(int));
    k_convert<<<eblocks, 256>>>(edges);
    k_scan1<<<SCAN_NB, 1024>>>();
    k_scan2<<<1, 128>>>();
    k_scan3<<<SCAN_NB, 1024>>>();
    k_fill<<<eblocks, 256>>>();

    dim3 ggrid((NN + 127) / 128, 2);

    // layer 0
    k_gemm<<<ggrid, 256, SMEM_BYTES>>>(x, Wrel0, Wroot0);
    k_gather<<<(NN + 7) / 8, 256>>>(b0, (float*)pA, 1);
    // layer 1
    k_gemm<<<ggrid, 256, SMEM_BYTES>>>((const float*)pA, Wrel1, Wroot1);
    k_gather<<<(NN + 7) / 8, 256>>>(b1, (float*)pB, 1);
    // layer 2 (no relu)
    k_gemm<<<ggrid, 256, SMEM_BYTES>>>((const float*)pB, Wrel2, Wroot2);
    k_gather<<<(NN + 7) / 8, 256>>>(b2, (float*)d_out, 0);
}

// round 4
// speedup vs baseline: 1.6482x; 1.2512x over previous
#include <cuda_runtime.h>
#include <cstdint>

#define NN 100000
#define NE 640000
#define HID 128
#define SCAN_NB 98   // 98 * 1024 >= NN

// ---------------- device scratch (static: no allocs allowed) ----------------
__device__ int   g_is64;
__device__ int   g_src[NE];
__device__ int   g_dst[NE];
__device__ int   g_deg[NN];
__device__ int   g_part[SCAN_NB];
__device__ int   g_partpre[SCAN_NB];
__device__ int   g_rowptr[NN + 1];
__device__ int   g_cursor[NN];
__device__ int   g_csr[NE];
__device__ float g_z[(size_t)NN * HID];   // x @ W_rel^T
__device__ float g_r[(size_t)NN * HID];   // x @ W_root^T
__device__ float g_hA[(size_t)NN * HID];  // layer0 output
__device__ float g_hB[(size_t)NN * HID];  // layer1 output

// ---------------- helpers ----------------
__device__ __forceinline__ float tf32f(float x) {
    unsigned u;
    asm("cvt.rna.tf32.f32 %0, %1;" : "=r"(u) : "f"(x));
    return __uint_as_float(u);
}

__device__ __forceinline__ void mma_tf32(float c[4], const unsigned a[4], const unsigned b[2]) {
    asm volatile(
        "mma.sync.aligned.m16n8k8.row.col.f32.tf32.tf32.f32 "
        "{%0,%1,%2,%3}, {%4,%5,%6,%7}, {%8,%9}, {%0,%1,%2,%3};\n"
        : "+f"(c[0]), "+f"(c[1]), "+f"(c[2]), "+f"(c[3])
        : "r"(a[0]), "r"(a[1]), "r"(a[2]), "r"(a[3]), "r"(b[0]), "r"(b[1]));
}

// ---------------- edge dtype detect + normalize ----------------
__global__ void k_detect(const int* __restrict__ e) {
    int zeros = 0;
    for (int i = 1; i < 256; i += 2) zeros += (e[i] == 0);
    g_is64 = (zeros > 100) ? 1 : 0;
}

__global__ void k_convert(const int* __restrict__ e) {
    int i = blockIdx.x * 256 + threadIdx.x;
    if (i >= NE) return;
    int s, d;
    if (g_is64) {
        s = e[2 * i];
        d = e[2 * NE + 2 * i];
    } else {
        s = e[i];
        d = e[NE + i];
    }
    g_src[i] = s;
    g_dst[i] = d;
    atomicAdd(&g_deg[d], 1);
}

// ---------------- 3-phase parallel exclusive scan ----------------
__global__ __launch_bounds__(1024) void k_scan1() {
    __shared__ int sh[1024];
    int i = blockIdx.x * 1024 + threadIdx.x;
    int v = (i < NN) ? g_deg[i] : 0;
    sh[threadIdx.x] = v;
    __syncthreads();
    #pragma unroll
    for (int off = 512; off > 0; off >>= 1) {
        if (threadIdx.x < off) sh[threadIdx.x] += sh[threadIdx.x + off];
        __syncthreads();
    }
    if (threadIdx.x == 0) g_part[blockIdx.x] = sh[0];
}

__global__ void k_scan2() {
    __shared__ int sh[128];
    int t = threadIdx.x;
    int v = (t < SCAN_NB) ? g_part[t] : 0;
    sh[t] = v;
    __syncthreads();
    #pragma unroll
    for (int off = 1; off < 128; off <<= 1) {
        int add = (t >= off) ? sh[t - off] : 0;
        __syncthreads();
        sh[t] += add;
        __syncthreads();
    }
    if (t < SCAN_NB) g_partpre[t] = sh[t] - v;
    if (t == 127) g_rowptr[NN] = sh[127];
}

__global__ __launch_bounds__(1024) void k_scan3() {
    __shared__ int sh[1024];
    int t = threadIdx.x;
    int i = blockIdx.x * 1024 + t;
    int v = (i < NN) ? g_deg[i] : 0;
    sh[t] = v;
    __syncthreads();
    #pragma unroll
    for (int off = 1; off < 1024; off <<= 1) {
        int add = (t >= off) ? sh[t - off] : 0;
        __syncthreads();
        sh[t] += add;
        __syncthreads();
    }
    if (i < NN) {
        int excl = sh[t] - v + g_partpre[blockIdx.x];
        g_rowptr[i] = excl;
        g_cursor[i] = excl;
    }
}

__global__ void k_fill() {
    int i = blockIdx.x * 256 + threadIdx.x;
    if (i < NE) {
        int d = g_dst[i];
        int p = atomicAdd(&g_cursor[d], 1);
        g_csr[p] = g_src[i];
    }
}

// ---------------- GEMM: Out(100k x 128) = X(100k x 128) @ W^T ----------------
// blockIdx.y == 0 : W = Wrel -> g_z ; blockIdx.y == 1 : W = Wroot -> g_r
// Single tf32 pass (A and W both tf32-rounded). 512 threads, 16 warps (4x4),
// warp tile 32x32, K=128 resident in smem.
#define APAD 132
#define SMEM_BYTES (2 * 128 * APAD * 4)

__global__ __launch_bounds__(512, 1) void k_gemm(const float* __restrict__ X,
                                                 const float* __restrict__ Wrel,
                                                 const float* __restrict__ Wroot) {
    extern __shared__ float sm[];
    float* As = sm;                  // 128 x APAD (tf32-rounded X tile)
    float* Bs = As + 128 * APAD;     // 128 x APAD (tf32-rounded W)

    const int tid = threadIdx.x;
    const int m0 = blockIdx.x * 128;
    const float* W = (blockIdx.y == 0) ? Wrel : Wroot;
    float* Out = (blockIdx.y == 0) ? g_z : g_r;

    const float4* X4 = (const float4*)X;
    #pragma unroll
    for (int t = tid; t < 128 * 32; t += 512) {
        int row = t >> 5, c4 = t & 31;
        float4 v = make_float4(0.f, 0.f, 0.f, 0.f);
        if (m0 + row < NN) v = X4[(size_t)(m0 + row) * 32 + c4];
        int base = row * APAD + c4 * 4;
        As[base + 0] = tf32f(v.x);
        As[base + 1] = tf32f(v.y);
        As[base + 2] = tf32f(v.z);
        As[base + 3] = tf32f(v.w);
    }
    const float4* W4 = (const float4*)W;
    #pragma unroll
    for (int t = tid; t < 128 * 32; t += 512) {
        int row = t >> 5, c4 = t & 31;
        float4 v = W4[t];
        int base = row * APAD + c4 * 4;
        Bs[base + 0] = tf32f(v.x);
        Bs[base + 1] = tf32f(v.y);
        Bs[base + 2] = tf32f(v.z);
        Bs[base + 3] = tf32f(v.w);
    }
    __syncthreads();

    const int wid = tid >> 5, lane = tid & 31;
    const int wm = wid >> 2, wn = wid & 3;          // 4x4 warp grid
    const int gid = lane >> 2, tig = lane & 3;

    float acc[2][4][4];
    #pragma unroll
    for (int mi = 0; mi < 2; mi++)
        #pragma unroll
        for (int ni = 0; ni < 4; ni++)
            #pragma unroll
            for (int q = 0; q < 4; q++) acc[mi][ni][q] = 0.f;

    #pragma unroll
    for (int kk = 0; kk < 128; kk += 8) {
        unsigned a[2][4], b[4][2];
        #pragma unroll
        for (int mi = 0; mi < 2; mi++) {
            int r0 = (wm * 32 + mi * 16 + gid) * APAD + kk + tig;
            a[mi][0] = __float_as_uint(As[r0]);
            a[mi][1] = __float_as_uint(As[r0 + 8 * APAD]);
            a[mi][2] = __float_as_uint(As[r0 + 4]);
            a[mi][3] = __float_as_uint(As[r0 + 8 * APAD + 4]);
        }
        #pragma unroll
        for (int ni = 0; ni < 4; ni++) {
            int c0 = (wn * 32 + ni * 8 + gid) * APAD + kk + tig;
            b[ni][0] = __float_as_uint(Bs[c0]);
            b[ni][1] = __float_as_uint(Bs[c0 + 4]);
        }
        #pragma unroll
        for (int mi = 0; mi < 2; mi++)
            #pragma unroll
            for (int ni = 0; ni < 4; ni++) mma_tf32(acc[mi][ni], a[mi], b[ni]);
    }

    #pragma unroll
    for (int mi = 0; mi < 2; mi++) {
        int rbase = m0 + wm * 32 + mi * 16 + gid;
        #pragma unroll
        for (int ni = 0; ni < 4; ni++) {
            int col = wn * 32 + ni * 8 + 2 * tig;
            if (rbase < NN)
                *(float2*)&Out[(size_t)rbase * HID + col] =
                    make_float2(acc[mi][ni][0], acc[mi][ni][1]);
            if (rbase + 8 < NN)
                *(float2*)&Out[(size_t)(rbase + 8) * HID + col] =
                    make_float2(acc[mi][ni][2], acc[mi][ni][3]);
        }
    }
}

// ---------------- gather: out[i] = [relu](r[i] + sum_{e in CSR[i]} z[src_e] + b)
__global__ __launch_bounds__(256) void k_gather(const float* __restrict__ bias,
                                                float* __restrict__ out, int do_relu) {
    int gw = (blockIdx.x * blockDim.x + threadIdx.x) >> 5;
    int lane = threadIdx.x & 31;
    if (gw >= NN) return;

    int beg = g_rowptr[gw], end = g_rowptr[gw + 1];
    const float4* z4 = (const float4*)g_z;

    float4 a0 = make_float4(0.f, 0.f, 0.f, 0.f);
    float4 a1 = make_float4(0.f, 0.f, 0.f, 0.f);
    int e = beg;
    for (; e + 1 < end; e += 2) {
        int s0 = g_csr[e], s1 = g_csr[e + 1];
        float4 v0 = z4[(size_t)s0 * 32 + lane];
        float4 v1 = z4[(size_t)s1 * 32 + lane];
        a0.x += v0.x; a0.y += v0.y; a0.z += v0.z; a0.w += v0.w;
        a1.x += v1.x; a1.y += v1.y; a1.z += v1.z; a1.w += v1.w;
    }
    if (e < end) {
        int s = g_csr[e];
        float4 v = z4[(size_t)s * 32 + lane];
        a0.x += v.x; a0.y += v.y; a0.z += v.z; a0.w += v.w;
    }

    float4 rr = ((const float4*)g_r)[(size_t)gw * 32 + lane];
    float4 bb = ((const float4*)bias)[lane];
    float4 o;
    o.x = a0.x + a1.x + rr.x + bb.x;
    o.y = a0.y + a1.y + rr.y + bb.y;
    o.z = a0.z + a1.z + rr.z + bb.z;
    o.w = a0.w + a1.w + rr.w + bb.w;
    if (do_relu) {
        o.x = fmaxf(o.x, 0.f);
        o.y = fmaxf(o.y, 0.f);
        o.z = fmaxf(o.z, 0.f);
        o.w = fmaxf(o.w, 0.f);
    }
    ((float4*)out)[(size_t)gw * 32 + lane] = o;
}

// ---------------- launch ----------------
extern "C" void kernel_launch(void* const* d_in, const int* in_sizes, int n_in,
                              void* d_out, int out_size) {
    (void)in_sizes; (void)n_in; (void)out_size;
    const float* x      = (const float*)d_in[0];
    const int*   edges  = (const int*)d_in[1];
    const float* Wrel0  = (const float*)d_in[2];
    const float* b0     = (const float*)d_in[3];
    const float* Wroot0 = (const float*)d_in[4];
    const float* Wrel1  = (const float*)d_in[5];
    const float* b1     = (const float*)d_in[6];
    const float* Wroot1 = (const float*)d_in[7];
    const float* Wrel2  = (const float*)d_in[8];
    const float* b2     = (const float*)d_in[9];
    const float* Wroot2 = (const float*)d_in[10];

    cudaFuncSetAttribute(k_gemm, cudaFuncAttributeMaxDynamicSharedMemorySize, SMEM_BYTES);

    void *pA = nullptr, *pB = nullptr, *pDeg = nullptr;
    cudaGetSymbolAddress(&pA, g_hA);
    cudaGetSymbolAddress(&pB, g_hB);
    cudaGetSymbolAddress(&pDeg, g_deg);

    const int eblocks = (NE + 255) / 256;
    k_detect<<<1, 1>>>(edges);
    cudaMemsetAsync(pDeg, 0, (size_t)NN * sizeof(int));
    k_convert<<<eblocks, 256>>>(edges);
    k_scan1<<<SCAN_NB, 1024>>>();
    k_scan2<<<1, 128>>>();
    k_scan3<<<SCAN_NB, 1024>>>();
    k_fill<<<eblocks, 256>>>();

    dim3 ggrid((NN + 127) / 128, 2);

    // layer 0
    k_gemm<<<ggrid, 512, SMEM_BYTES>>>(x, Wrel0, Wroot0);
    k_gather<<<(NN + 7) / 8, 256>>>(b0, (float*)pA, 1);
    // layer 1
    k_gemm<<<ggrid, 512, SMEM_BYTES>>>((const float*)pA, Wrel1, Wroot1);
    k_gather<<<(NN + 7) / 8, 256>>>(b1, (float*)pB, 1);
    // layer 2 (no relu)
    k_gemm<<<ggrid, 512, SMEM_BYTES>>>((const float*)pB, Wrel2, Wroot2);
    k_gather<<<(NN + 7) / 8, 256>>>(b2, (float*)d_out, 0);
}